// round 6
// baseline (speedup 1.0000x reference)
#include <cuda_runtime.h>
#include <cuda_bf16.h>
#include <math.h>

// ArcFace-style margin softmax cross-entropy loss (fused single kernel).
//   loss = mean_b [ logsumexp_c(logits[b,c]) - logits[b, label_b] ]
// logits = clip(cos,-1+eps,1-eps)*64; label column replaced by
// (ct*cos(m) - sqrt(1-ct^2)*sin(m))*64.
//
// Single pass, fixed-shift logsumexp (shift = 64 = max possible logit):
//   lse = 64 + log(sum exp(logit-64)); all exponents <= 0.
// exp(64x-64) computed as ex2(x*92.33248 - 92.33248)  (log2e folded in).
//
// Epilogue is warp-0-only: shuffle reductions, fence+atomic+last-block
// detection confined to one warp so warps 1..7 retire immediately
// (block-exit serialization was costing ~3.5us in the previous round).

#define EPS_CLIP 1e-7f
#define SCALE 64.0f
#define L2E_SCALE 92.33248262f   // 64 * log2(e)
#define TPB 256

static __device__ float g_row_loss[4096];          // per-row losses (B <= 4096)
static __device__ unsigned int g_done_count = 0;   // reset to 0 by last block

__device__ __forceinline__ float clipf(float x) {
    return fminf(fmaxf(x, -1.0f + EPS_CLIP), 1.0f - EPS_CLIP);
}

__device__ __forceinline__ float ex2_approx(float t) {
    float r;
    asm("ex2.approx.ftz.f32 %0, %1;" : "=f"(r) : "f"(t));
    return r;
}

// exp(clip(x)*64 - 64) = 2^(clip(x)*64*log2e - 64*log2e)
__device__ __forceinline__ float term(float x) {
    return ex2_approx(fmaf(clipf(x), L2E_SCALE, -L2E_SCALE));
}

__global__ void __launch_bounds__(TPB) margin_loss_fused_kernel(
    const float* __restrict__ cos_theta,
    const int* __restrict__ labels,
    const float* __restrict__ margins,
    float* __restrict__ out,
    int B, int C)
{
    const int row = blockIdx.x;
    const int tid = threadIdx.x;
    const int lane = tid & 31;
    const int wid = tid >> 5;
    const size_t row_off = (size_t)row * (size_t)C;
    const float4* rp = reinterpret_cast<const float4*>(cos_theta + row_off);
    const int n4 = C >> 2;

    float acc = 0.0f;
    // strided float4 loads; fixed per-thread order -> deterministic.
    // (This exact loop shape measured 6.33 TB/s in round 2.)
    for (int i = tid; i < n4; i += TPB) {
        float4 v = rp[i];
        acc += term(v.x);
        acc += term(v.y);
        acc += term(v.z);
        acc += term(v.w);
    }
    // scalar tail (C % 4)
    for (int i = (n4 << 2) + tid; i < C; i += TPB) {
        acc += term(cos_theta[row_off + i]);
    }

    // intra-warp shuffle reduction (deterministic fixed order)
    #pragma unroll
    for (int off = 16; off > 0; off >>= 1)
        acc += __shfl_xor_sync(0xffffffffu, acc, off);

    __shared__ float warp_sum[TPB / 32];
    if (lane == 0) warp_sum[wid] = acc;
    __syncthreads();   // warps 1..7 are done after this and retire

    if (wid == 0) {
        // reduce the 8 warp partials within warp 0 (lanes 0..7 hold data)
        float s = (lane < TPB / 32) ? warp_sum[lane] : 0.0f;
        #pragma unroll
        for (int off = 4; off > 0; off >>= 1)
            s += __shfl_xor_sync(0xffffffffu, s, off);

        unsigned int is_last = 0;
        if (lane == 0) {
            int lab = labels[row];
            float cl = clipf(cos_theta[row_off + (size_t)lab]);
            float m = margins[lab];
            float cm = cosf(m);
            float sm = sinf(m);
            float sin_l = sqrtf(fmaxf(1.0f - cl * cl, 0.0f));
            float target = cl * cm - sin_l * sm;      // cos(theta + m)
            float target_logit = target * SCALE;

            // swap label-column contribution (term() cancels exactly)
            float sum = s
                      + ex2_approx(fmaf(target, L2E_SCALE, -L2E_SCALE))
                      - term(cl);

            g_row_loss[row] = (SCALE + logf(sum)) - target_logit;

            __threadfence();
            unsigned int prev = atomicAdd(&g_done_count, 1u);
            is_last = (prev == (unsigned int)(gridDim.x - 1)) ? 1u : 0u;
        }
        is_last = __shfl_sync(0xffffffffu, is_last, 0);

        if (is_last) {
            __threadfence();  // acquire side of the producer fences
            // warp-0-only deterministic reduction over all row losses
            float r = 0.0f;
            for (int j = lane; j < B; j += 32)
                r += __ldcg(&g_row_loss[j]);
            #pragma unroll
            for (int off = 16; off > 0; off >>= 1)
                r += __shfl_xor_sync(0xffffffffu, r, off);
            if (lane == 0) {
                out[0] = r / (float)B;
                g_done_count = 0;   // reset for next graph replay
            }
        }
    }
}

extern "C" void kernel_launch(void* const* d_in, const int* in_sizes, int n_in,
                              void* d_out, int out_size)
{
    const float* cos_theta = (const float*)d_in[0];
    const int*   labels    = (const int*)d_in[1];
    const float* margins   = (const float*)d_in[2];
    float* out = (float*)d_out;

    const int B = in_sizes[1];
    const int C = in_sizes[0] / B;

    margin_loss_fused_kernel<<<B, TPB>>>(cos_theta, labels, margins, out, B, C);
}